// round 8
// baseline (speedup 1.0000x reference)
#include <cuda_runtime.h>
#include <cuda_bf16.h>

// Problem constants (fixed by setup_inputs)
#define B_   8
#define T_   2048
#define C_   256
#define L_   32
#define DQ_  512
#define NW_  2017      // T - 32 + 1
#define STOT_ 2045     // T - 4 + 1  (s = w + 4j range)

typedef unsigned long long ull;

// Scratch (device globals: no allocations allowed)
__device__ float g_part1[16 * 65536];  // k-split partials for enc1 (4 MB)
__device__ float g_part2[16 * 65536];  // k-split partials for enc2
__device__ float g_enc1[65536];        // (B*L, C)
__device__ float g_enc2[65536];
__device__ int   g_labels[B_ * T_];

// ---- f32x2 packed helpers (FFMA2: only reachable via PTX fma.rn.f32x2) ----
__device__ __forceinline__ ull pack2(float x, float y) {
    ull r; asm("mov.b64 %0, {%1, %2};" : "=l"(r) : "f"(x), "f"(y)); return r;
}
__device__ __forceinline__ void unpack2(ull v, float& x, float& y) {
    asm("mov.b64 {%0, %1}, %2;" : "=f"(x), "=f"(y) : "l"(v));
}
__device__ __forceinline__ ull fma2(ull a, ull b, ull c) {
    ull d; asm("fma.rn.f32x2 %0, %1, %2, %3;" : "=l"(d) : "l"(a), "l"(b), "l"(c)); return d;
}

// ---------------------------------------------------------------------------
// Kernel A1: partial GEMMs  enc = query @ W  (K split into 16 ranges of 32)
// grid (16 ksplit, 32 l), block 256 (thread = c). 8 b-rows per block.
// f32x2 pairs are across output rows (bb) -> bitwise identical to scalar.
// ---------------------------------------------------------------------------
__global__ void gemm_part(const float* __restrict__ query,
                          const float* __restrict__ W1,
                          const float* __restrict__ W2) {
    __shared__ __align__(16) float qsT[32 * 8];   // qsT[d][bb]
    const int l   = blockIdx.y;
    const int k0  = blockIdx.x * 32;
    const int tid = threadIdx.x;

    if (tid < 256) {
        int d = tid >> 3, bb = tid & 7;
        qsT[d * 8 + bb] = query[(bb * L_ + l) * DQ_ + k0 + d];
    }
    __syncthreads();

    const int c = tid;
    const ull z = pack2(0.f, 0.f);
    ull a1[4] = {z, z, z, z};
    ull a2[4] = {z, z, z, z};

#pragma unroll 8
    for (int d = 0; d < 32; ++d) {
        float w1 = W1[(k0 + d) * C_ + c];
        float w2 = W2[(k0 + d) * C_ + c];
        ull ww1 = pack2(w1, w1);
        ull ww2 = pack2(w2, w2);
        const ull* q2 = (const ull*)&qsT[d * 8];
        ull q0 = q2[0], q1 = q2[1], q2v = q2[2], q3 = q2[3];
        a1[0] = fma2(q0, ww1, a1[0]);
        a1[1] = fma2(q1, ww1, a1[1]);
        a1[2] = fma2(q2v, ww1, a1[2]);
        a1[3] = fma2(q3, ww1, a1[3]);
        a2[0] = fma2(q0, ww2, a2[0]);
        a2[1] = fma2(q1, ww2, a2[1]);
        a2[2] = fma2(q2v, ww2, a2[2]);
        a2[3] = fma2(q3, ww2, a2[3]);
    }

    const int kidx = blockIdx.x;
#pragma unroll
    for (int j = 0; j < 4; ++j) {
        float x, y;
        unpack2(a1[j], x, y);
        g_part1[kidx * 65536 + ((2 * j) * L_ + l) * C_ + c]     = x;
        g_part1[kidx * 65536 + ((2 * j + 1) * L_ + l) * C_ + c] = y;
        unpack2(a2[j], x, y);
        g_part2[kidx * 65536 + ((2 * j) * L_ + l) * C_ + c]     = x;
        g_part2[kidx * 65536 + ((2 * j + 1) * L_ + l) * C_ + c] = y;
    }
}

// ---------------------------------------------------------------------------
// Kernel A2: deterministic reduce of k-split partials + bias
// ---------------------------------------------------------------------------
__global__ void gemm_reduce(const float* __restrict__ b1,
                            const float* __restrict__ b2) {
    int i = blockIdx.x * 256 + threadIdx.x;   // 0..65535
    int c = i & (C_ - 1);
    float s1 = b1[c], s2 = b2[c];
#pragma unroll
    for (int k = 0; k < 16; ++k) {
        s1 += g_part1[k * 65536 + i];
        s2 += g_part2[k * 65536 + i];
    }
    g_enc1[i] = s1;
    g_enc2[i] = s2;
}

// ---------------------------------------------------------------------------
// Kernel B v3: clip_labels[b,t] = argmax_l  vis[b,t,:] . enc1[b,l,:]
// grid (8 b, 64 t-tiles of 32), block 256 = 8 warps; warp = c-chunk of 32
// (uniform per warp -> broadcast LDS on enc1), lane = t-slot.
// Partials through the same 32KB buffer, layout [l*8+ch][lane]: contiguous
// lanes -> conflict-free writes AND reads. Two-stage argmax keeps jnp
// first-max tie semantics (ascending l, strict >).
// ---------------------------------------------------------------------------
__global__ void labels_kernel(const float* __restrict__ vis) {
    __shared__ __align__(16) float sbuf[8192];   // 32 KB: enc1[b], then partials
    __shared__ float sbv[256];
    __shared__ int   sbi[256];
    const int b     = blockIdx.x;
    const int tbase = blockIdx.y * 32;
    const int tid   = threadIdx.x;
    const int lane  = tid & 31;
    const int chunk = tid >> 5;                  // 0..7 (c in [chunk*32, +32))
    const int t     = tbase + lane;

    // stage enc1[b] (32 KB)
    {
        const float4* src = (const float4*)g_enc1 + b * 2048;
        float4* dst = (float4*)sbuf;
        for (int i = tid; i < 2048; i += 256) dst[i] = src[i];
    }
    __syncthreads();

    const float4* v4 = (const float4*)(vis + ((size_t)b * T_ + t) * C_) + chunk * 8;
    const float4* e4 = (const float4*)sbuf + chunk * 8;

    float acc[L_];
#pragma unroll
    for (int l = 0; l < L_; ++l) acc[l] = 0.f;

#pragma unroll
    for (int c0 = 0; c0 < 8; ++c0) {
        float4 v = v4[c0];
#pragma unroll
        for (int l = 0; l < L_; ++l) {
            float4 e = e4[l * 64 + c0];          // uniform across warp -> broadcast
            acc[l] += v.x * e.x + v.y * e.y + v.z * e.z + v.w * e.w;
        }
    }

    __syncthreads();   // everyone done reading enc1 -> reuse sbuf
#pragma unroll
    for (int l = 0; l < L_; ++l)
        sbuf[(l * 8 + chunk) * 32 + lane] = acc[l];   // conflict-free
    __syncthreads();

    // warp 'chunk' reduces l in [chunk*4, chunk*4+4) for all 32 t (lane = t)
    float best = -3.0e38f;
    int   bi   = 0;
#pragma unroll
    for (int li = 0; li < 4; ++li) {
        int l = chunk * 4 + li;
        float s = 0.f;
#pragma unroll
        for (int ch = 0; ch < 8; ++ch)
            s += sbuf[(l * 8 + ch) * 32 + lane];      // conflict-free
        if (s > best) { best = s; bi = l; }
    }
    sbv[chunk * 32 + lane] = best;
    sbi[chunk * 32 + lane] = bi;
    __syncthreads();

    if (chunk == 0) {
        float bv = sbv[lane];
        int   bl = sbi[lane];
#pragma unroll
        for (int g = 1; g < 8; ++g) {                 // ascending l-groups
            float ov = sbv[g * 32 + lane];
            int   oi = sbi[g * 32 + lane];
            if (ov > bv) { bv = ov; bl = oi; }        // strict > keeps first max
        }
        g_labels[b * T_ + tbase + lane] = bl;
    }
}

// ---------------------------------------------------------------------------
// Kernel D v3: out[b,w,j,c] = enc2[b, maj4(labels[b,s..s+3]), c]
//              * (vis[b,s,c]+..+vis[b,s+3,c]) / 4,  s = w + 4j.
// grid (128 s-tiles of 16, 8 b) = 1024 blocks, block 256 = 4 s-groups x 64 c4.
// Each s-group walks 4 consecutive s with a register sliding window of 4 vis
// rows. enc2[b] staged once per block. Output stores via __stcs (streaming)
// to keep vis/enc2 resident in L2. All stores coalesced STG.128.
// ---------------------------------------------------------------------------
__global__ void out_kernel(const float* __restrict__ vis,
                           float* __restrict__ out) {
    __shared__ float4 e2s[2048];   // 32 KB
    const int b   = blockIdx.y;
    const int tid = threadIdx.x;

    const float4* e2g = (const float4*)g_enc2 + b * 2048;
    for (int i = tid; i < 2048; i += 256) e2s[i] = e2g[i];
    __syncthreads();

    const int sgrp = tid >> 6;                 // 0..3
    const int c4   = tid & 63;
    const int s0   = blockIdx.x * 16 + sgrp * 4;

    // prefetch the 7 labels this s-group can touch (uniform across c4 lanes)
    int la[7];
    const int* lab = g_labels + b * T_ + s0;
#pragma unroll
    for (int k = 0; k < 7; ++k)
        la[k] = (s0 + k < T_) ? lab[k] : 0;

    const float4* vp = (const float4*)vis + ((size_t)b * T_ + s0) * 64 + c4;
    float4 w0 = vp[0], w1 = vp[64], w2 = vp[128], w3 = vp[192];
    float4* o = (float4*)out;

#pragma unroll
    for (int i = 0; i < 4; ++i) {
        const int s = s0 + i;
        if (s >= STOT_) break;

        // majority of labels[s..s+3]; ties -> smallest label value
        int l0 = la[i], l1 = la[i + 1], l2 = la[i + 2], l3 = la[i + 3];
        int n0 = (l0 == l1) + (l0 == l2) + (l0 == l3);
        int n1 = (l1 == l0) + (l1 == l2) + (l1 == l3);
        int n2 = (l2 == l0) + (l2 == l1) + (l2 == l3);
        int n3 = (l3 == l0) + (l3 == l1) + (l3 == l2);
        int maj = l0, bc = n0;
        if (n1 > bc || (n1 == bc && l1 < maj)) { bc = n1; maj = l1; }
        if (n2 > bc || (n2 == bc && l2 < maj)) { bc = n2; maj = l2; }
        if (n3 > bc || (n3 == bc && l3 < maj)) { bc = n3; maj = l3; }

        float4 e = e2s[maj * 64 + c4];
        float4 g;
        g.x = e.x * (w0.x + w1.x + w2.x + w3.x) * 0.25f;
        g.y = e.y * (w0.y + w1.y + w2.y + w3.y) * 0.25f;
        g.z = e.z * (w0.z + w1.z + w2.z + w3.z) * 0.25f;
        g.w = e.w * (w0.w + w1.w + w2.w + w3.w) * 0.25f;

        const int jhi = min(7, s >> 2);
        const int jlo = (s > NW_ - 1) ? ((s - (NW_ - 1) + 3) >> 2) : 0;
#pragma unroll
        for (int j = jlo; j <= jhi; ++j) {
            int w = s - 4 * j;
            __stcs(&o[(((size_t)b * NW_ + w) * 8 + j) * 64 + c4], g);
        }

        // slide window: drop row s, load row s+4 (for next s)
        w0 = w1; w1 = w2; w2 = w3;
        if (i < 3 && s + 4 < T_) w3 = vp[(i + 4) * 64];
    }
}

// ---------------------------------------------------------------------------
extern "C" void kernel_launch(void* const* d_in, const int* in_sizes, int n_in,
                              void* d_out, int out_size) {
    (void)in_sizes; (void)n_in; (void)out_size;
    const float* vis   = (const float*)d_in[0];
    const float* query = (const float*)d_in[1];
    const float* W1    = (const float*)d_in[2];
    const float* b1    = (const float*)d_in[3];
    const float* W2    = (const float*)d_in[4];
    const float* b2    = (const float*)d_in[5];

    gemm_part    <<<dim3(16, 32), 256>>>(query, W1, W2);
    gemm_reduce  <<<256,          256>>>(b1, b2);
    labels_kernel<<<dim3(8, 64),  256>>>(vis);
    out_kernel   <<<dim3(128, 8), 256>>>(vis, (float*)d_out);
}

// round 12
// speedup vs baseline: 1.3034x; 1.3034x over previous
#include <cuda_runtime.h>
#include <cuda_bf16.h>

// Problem constants (fixed by setup_inputs)
#define B_   8
#define T_   2048
#define C_   256
#define L_   32
#define DQ_  512
#define NW_  2017      // T - 32 + 1
#define STOT_ 2045     // T - 4 + 1  (s = w + 4j range)

// Scratch (device globals: no allocations allowed)
__device__ float g_part1[8 * 65536];   // k-split partials for enc1
__device__ float g_part2[8 * 65536];   // k-split partials for enc2
__device__ float g_enc1[65536];        // (B*L, C)
__device__ float g_enc2[65536];
__device__ int   g_labels[B_ * T_];

// ---------------------------------------------------------------------------
// Kernel A1: partial GEMMs  enc = query @ W  (K split into 8 ranges of 64)
// grid (8 ksplit, 32 l), block 256 (thread = c). 8 b-rows per block.
// ---------------------------------------------------------------------------
__global__ void gemm_part(const float* __restrict__ query,
                          const float* __restrict__ W1,
                          const float* __restrict__ W2) {
    __shared__ float qsT[64 * 8];   // qsT[d][bb]
    const int l   = blockIdx.y;
    const int k0  = blockIdx.x * 64;
    const int tid = threadIdx.x;

    for (int i = tid; i < 512; i += 256) {
        int d = i >> 3, bb = i & 7;
        qsT[d * 8 + bb] = query[(bb * L_ + l) * DQ_ + k0 + d];
    }
    __syncthreads();

    const int c = tid;
    float a1[8], a2[8];
#pragma unroll
    for (int i = 0; i < 8; ++i) { a1[i] = 0.f; a2[i] = 0.f; }

#pragma unroll 4
    for (int d = 0; d < 64; ++d) {
        float w1 = W1[(k0 + d) * C_ + c];
        float w2 = W2[(k0 + d) * C_ + c];
        float4 qa = *(const float4*)&qsT[d * 8];
        float4 qb = *(const float4*)&qsT[d * 8 + 4];
        a1[0] += qa.x * w1; a1[1] += qa.y * w1; a1[2] += qa.z * w1; a1[3] += qa.w * w1;
        a1[4] += qb.x * w1; a1[5] += qb.y * w1; a1[6] += qb.z * w1; a1[7] += qb.w * w1;
        a2[0] += qa.x * w2; a2[1] += qa.y * w2; a2[2] += qa.z * w2; a2[3] += qa.w * w2;
        a2[4] += qb.x * w2; a2[5] += qb.y * w2; a2[6] += qb.z * w2; a2[7] += qb.w * w2;
    }

    const int kidx = blockIdx.x;
#pragma unroll
    for (int bb = 0; bb < 8; ++bb) {
        int row = bb * L_ + l;
        g_part1[kidx * 65536 + row * C_ + c] = a1[bb];
        g_part2[kidx * 65536 + row * C_ + c] = a2[bb];
    }
}

// ---------------------------------------------------------------------------
// Kernel A2: deterministic reduce of k-split partials + bias
// ---------------------------------------------------------------------------
__global__ void gemm_reduce(const float* __restrict__ b1,
                            const float* __restrict__ b2) {
    int i = blockIdx.x * 256 + threadIdx.x;   // 0..65535
    int c = i & (C_ - 1);
    float s1 = b1[c], s2 = b2[c];
#pragma unroll
    for (int k = 0; k < 8; ++k) {
        s1 += g_part1[k * 65536 + i];
        s2 += g_part2[k * 65536 + i];
    }
    g_enc1[i] = s1;
    g_enc2[i] = s2;
}

// ---------------------------------------------------------------------------
// Kernel B v2: clip_labels[b,t] = argmax_l  vis[b,t,:] . enc1[b,l,:]
// grid (8 b, 32 t-tiles of 64), block 256 = 64 t x 4 c-chunks of 64.
// Warp layout: wid>>1 = chunk (uniform per warp -> broadcast LDS on enc1),
// p = (wid&1)*32+lane = t-slot. Cross-chunk reduce through the SAME 32KB
// smem buffer, layout [l*4+ch][t], then argmax with shfl combine.
// ---------------------------------------------------------------------------
__global__ void labels_kernel(const float* __restrict__ vis) {
    __shared__ __align__(16) float sbuf[8192];   // 32 KB: enc1[b], then partials
    const int b     = blockIdx.x;
    const int tbase = blockIdx.y * 64;
    const int tid   = threadIdx.x;
    const int lane  = tid & 31;
    const int wid   = tid >> 5;
    const int chunk = wid >> 1;                  // 0..3  (c in [chunk*64, +64))
    const int p     = ((wid & 1) << 5) | lane;   // 0..63 t-slot
    const int t     = tbase + p;

    // stage enc1[b] (32 KB)
    {
        const float4* src = (const float4*)g_enc1 + b * 2048;
        float4* dst = (float4*)sbuf;
        for (int i = tid; i < 2048; i += 256) dst[i] = src[i];
    }
    __syncthreads();

    const float4* v4 = (const float4*)(vis + ((size_t)b * T_ + t) * C_) + chunk * 16;
    const float4* e4 = (const float4*)sbuf + chunk * 16;

    float acc[L_];
#pragma unroll
    for (int l = 0; l < L_; ++l) acc[l] = 0.f;

#pragma unroll 4
    for (int c0 = 0; c0 < 16; ++c0) {
        float4 v = v4[c0];
#pragma unroll
        for (int l = 0; l < L_; ++l) {
            float4 e = e4[l * 64 + c0];          // uniform across warp -> broadcast
            acc[l] += v.x * e.x + v.y * e.y + v.z * e.z + v.w * e.w;
        }
    }

    // everyone done reading enc1 -> reuse sbuf for partials
    __syncthreads();
#pragma unroll
    for (int l = 0; l < L_; ++l)
        sbuf[(l * 4 + chunk) * 64 + p] = acc[l];  // lanes p contiguous: conflict-free
    __syncthreads();

    // reduce: thread = (t2 = tid>>2, lg = tid&3 handling 8 l's)
    const int t2 = tid >> 2;
    const int lg = tid & 3;
    float best = -3.0e38f;
    int   bi   = 0;
#pragma unroll
    for (int li = 0; li < 8; ++li) {
        int l = lg * 8 + li;
        float s = sbuf[(l * 4 + 0) * 64 + t2]
                + sbuf[(l * 4 + 1) * 64 + t2]
                + sbuf[(l * 4 + 2) * 64 + t2]
                + sbuf[(l * 4 + 3) * 64 + t2];
        if (s > best) { best = s; bi = l; }
    }
    // combine the 4 l-groups (lanes differing in bits 0..1)
#pragma unroll
    for (int off = 1; off <= 2; off <<= 1) {
        float ov = __shfl_xor_sync(0xffffffffu, best, off);
        int   oi = __shfl_xor_sync(0xffffffffu, bi,   off);
        if (ov > best || (ov == best && oi < bi)) { best = ov; bi = oi; }
    }
    if (lg == 0) g_labels[b * T_ + tbase + t2] = bi;
}

// ---------------------------------------------------------------------------
// Kernel D v4: out[b,w,j,c] = enc2[b, maj4(labels[b,s..s+3]), c]
//              * (vis[b,s,c]+..+vis[b,s+3,c]) / 4,  s = w + 4j.
// ONE change vs the 29.7us R4 version: grid split over C-halves.
// grid (64 s-tiles of 32, 2 c-halves, 8 b) = 1024 blocks,
// block 256 = 8 s-groups x 32 lanes (c4 = half*32 + lane).
// Each block stages only HALF of enc2[b] (16 KB smem -> 8 blocks/SM,
// thread-limited, ~2x occupancy of R4). Plain STG.128 (no stcs).
// ---------------------------------------------------------------------------
__global__ void out_kernel(const float* __restrict__ vis,
                           float* __restrict__ out) {
    __shared__ float4 e2s[1024];   // 16 KB: half of enc2[b]
    const int b    = blockIdx.z;
    const int half = blockIdx.y;   // 0: c4 in [0,32), 1: c4 in [32,64)
    const int tid  = threadIdx.x;

    const float4* e2g = (const float4*)g_enc2 + b * 2048 + half * 32;
    for (int i = tid; i < 1024; i += 256) {
        int l = i >> 5, cc = i & 31;
        e2s[i] = e2g[l * 64 + cc];
    }
    __syncthreads();

    const int sgrp = tid >> 5;                 // 0..7
    const int lane = tid & 31;                 // c4 local
    const int c4   = half * 32 + lane;         // global float4 column
    const int s0   = blockIdx.x * 32 + sgrp * 4;

    // prefetch the 7 labels this s-group can touch (uniform across lanes)
    int la[7];
    const int* lab = g_labels + b * T_ + s0;
#pragma unroll
    for (int k = 0; k < 7; ++k)
        la[k] = (s0 + k < T_) ? lab[k] : 0;

    const float4* vp = (const float4*)vis + ((size_t)b * T_ + s0) * 64 + c4;
    float4 w0 = vp[0], w1 = vp[64], w2 = vp[128], w3 = vp[192];
    float4* o = (float4*)out;

#pragma unroll
    for (int i = 0; i < 4; ++i) {
        const int s = s0 + i;
        if (s >= STOT_) break;

        // majority of labels[s..s+3]; ties -> smallest label value
        int l0 = la[i], l1 = la[i + 1], l2 = la[i + 2], l3 = la[i + 3];
        int n0 = (l0 == l1) + (l0 == l2) + (l0 == l3);
        int n1 = (l1 == l0) + (l1 == l2) + (l1 == l3);
        int n2 = (l2 == l0) + (l2 == l1) + (l2 == l3);
        int n3 = (l3 == l0) + (l3 == l1) + (l3 == l2);
        int maj = l0, bc = n0;
        if (n1 > bc || (n1 == bc && l1 < maj)) { bc = n1; maj = l1; }
        if (n2 > bc || (n2 == bc && l2 < maj)) { bc = n2; maj = l2; }
        if (n3 > bc || (n3 == bc && l3 < maj)) { bc = n3; maj = l3; }

        float4 e = e2s[maj * 32 + lane];
        float4 g;
        g.x = e.x * (w0.x + w1.x + w2.x + w3.x) * 0.25f;
        g.y = e.y * (w0.y + w1.y + w2.y + w3.y) * 0.25f;
        g.z = e.z * (w0.z + w1.z + w2.z + w3.z) * 0.25f;
        g.w = e.w * (w0.w + w1.w + w2.w + w3.w) * 0.25f;

        const int jhi = min(7, s >> 2);
        const int jlo = (s > NW_ - 1) ? ((s - (NW_ - 1) + 3) >> 2) : 0;
#pragma unroll
        for (int j = jlo; j <= jhi; ++j) {
            int w = s - 4 * j;
            o[(((size_t)b * NW_ + w) * 8 + j) * 64 + c4] = g;
        }

        // slide window: drop row s, load row s+4 (for next s)
        w0 = w1; w1 = w2; w2 = w3;
        if (i < 3 && s + 4 < T_) w3 = vp[(i + 4) * 64];
    }
}

// ---------------------------------------------------------------------------
extern "C" void kernel_launch(void* const* d_in, const int* in_sizes, int n_in,
                              void* d_out, int out_size) {
    (void)in_sizes; (void)n_in; (void)out_size;
    const float* vis   = (const float*)d_in[0];
    const float* query = (const float*)d_in[1];
    const float* W1    = (const float*)d_in[2];
    const float* b1    = (const float*)d_in[3];
    const float* W2    = (const float*)d_in[4];
    const float* b2    = (const float*)d_in[5];

    gemm_part    <<<dim3(8, 32),     256>>>(query, W1, W2);
    gemm_reduce  <<<256,             256>>>(b1, b2);
    labels_kernel<<<dim3(8, 32),     256>>>(vis);
    out_kernel   <<<dim3(64, 2, 8),  256>>>(vis, (float*)d_out);
}